// round 13
// baseline (speedup 1.0000x reference)
#include <cuda_runtime.h>
#include <cuda_fp16.h>
#include <math.h>
#include <stdint.h>

// Problem constants
#define Bb   2
#define Ss   2048
#define Ee   768
#define Hh   12
#define Dd   64
#define FFf  3072
#define Mrows (Bb*Ss)   // 4096

// ---------------------------------------------------------------------------
// Scratch
// ---------------------------------------------------------------------------
__device__ __half g_xnh[Mrows*Ee];
__device__ __half g_qh [Mrows*Ee];
__device__ __half g_kh [Mrows*Ee];
__device__ __half g_vh [Mrows*Ee];
__device__ __half g_ath[Mrows*Ee];
__device__ float  g_res[Mrows*Ee];
__device__ __half g_yh [Mrows*Ee];
__device__ __half g_hbh[Mrows*FFf];
__device__ __half g_wqh[Ee*Ee];
__device__ __half g_wkh[Ee*Ee];
__device__ __half g_wvh[Ee*Ee];
__device__ __half g_woh[Ee*Ee];
__device__ __half g_w1h[FFf*Ee];
__device__ __half g_w2h[Ee*FFf];

// ---------------------------------------------------------------------------
// Helpers
// ---------------------------------------------------------------------------
__device__ __forceinline__ uint32_t smem_u32(const void* p) {
    uint32_t a;
    asm("{ .reg .u64 t; cvta.to.shared.u64 t, %1; cvt.u32.u64 %0, t; }"
        : "=r"(a) : "l"(p));
    return a;
}
__device__ __forceinline__ void cp16(uint32_t dst, const void* src) {
    asm volatile("cp.async.cg.shared.global [%0], [%1], 16;"
                 :: "r"(dst), "l"(src));
}
#define CP_COMMIT() asm volatile("cp.async.commit_group;" ::: "memory")
#define CP_WAIT(n)  asm volatile("cp.async.wait_group %0;" :: "n"(n) : "memory")

__device__ __forceinline__ void mma_f16(float* c, const uint32_t* a,
                                        uint32_t b0, uint32_t b1) {
    asm volatile(
        "mma.sync.aligned.m16n8k16.row.col.f32.f16.f16.f32 "
        "{%0,%1,%2,%3}, {%4,%5,%6,%7}, {%8,%9}, {%0,%1,%2,%3};"
        : "+f"(c[0]), "+f"(c[1]), "+f"(c[2]), "+f"(c[3])
        : "r"(a[0]), "r"(a[1]), "r"(a[2]), "r"(a[3]), "r"(b0), "r"(b1));
}
__device__ __forceinline__ void ldm_x4(uint32_t* r, uint32_t addr) {
    asm volatile("ldmatrix.sync.aligned.m8n8.x4.shared.b16 {%0,%1,%2,%3}, [%4];"
                 : "=r"(r[0]), "=r"(r[1]), "=r"(r[2]), "=r"(r[3]) : "r"(addr));
}
__device__ __forceinline__ void ldm_x4t(uint32_t* r, uint32_t addr) {
    asm volatile("ldmatrix.sync.aligned.m8n8.x4.trans.shared.b16 {%0,%1,%2,%3}, [%4];"
                 : "=r"(r[0]), "=r"(r[1]), "=r"(r[2]), "=r"(r[3]) : "r"(addr));
}
__device__ __forceinline__ uint32_t pack2(float a, float b) {
    __half2 h = __floats2half2_rn(a, b);
    return *(uint32_t*)&h;
}

// ---------------------------------------------------------------------------
// Fused weight conversion f32 -> f16 (one launch)
// ---------------------------------------------------------------------------
__global__ void convert_all(const float* __restrict__ wq, const float* __restrict__ wk,
                            const float* __restrict__ wv, const float* __restrict__ wo,
                            const float* __restrict__ w1, const float* __restrict__ w2,
                            __half* __restrict__ dq, __half* __restrict__ dk,
                            __half* __restrict__ dv, __half* __restrict__ dwo,
                            __half* __restrict__ d1, __half* __restrict__ d2)
{
    const int E4 = Ee * Ee / 4;
    const int F4 = (FFf * Ee) / 4;
    int i = blockIdx.x * blockDim.x + threadIdx.x;
    const float* s; __half* d;
    if      (i < E4)          { s = wq; d = dq; }
    else if (i < 2*E4)        { s = wk; d = dk;  i -= E4; }
    else if (i < 3*E4)        { s = wv; d = dv;  i -= 2*E4; }
    else if (i < 4*E4)        { s = wo; d = dwo; i -= 3*E4; }
    else if (i < 4*E4 + F4)   { s = w1; d = d1;  i -= 4*E4; }
    else                      { s = w2; d = d2;  i -= 4*E4 + F4; }
    float4 v = ((const float4*)s)[i];
    __half2* o = (__half2*)(d + i * 4);
    o[0] = __floats2half2_rn(v.x, v.y);
    o[1] = __floats2half2_rn(v.z, v.w);
}
#define CONV_BLOCKS ((4*(Ee*Ee/4) + 2*((FFf*Ee)/4)) / 256)

// ---------------------------------------------------------------------------
// LayerNorm (f32 in, f16 out)
// ---------------------------------------------------------------------------
__global__ void ln_kernel(const float* __restrict__ X,
                          const float* __restrict__ gamma,
                          const float* __restrict__ beta,
                          __half* __restrict__ Y)
{
    const int row = blockIdx.x;
    const float* x = X + (size_t)row * Ee;
    __half*      y = Y + (size_t)row * Ee;
    const int t = threadIdx.x;

    float v0 = x[t], v1 = x[t + 256], v2 = x[t + 512];
    float s  = v0 + v1 + v2;

    __shared__ float red[8];
    #pragma unroll
    for (int off = 16; off; off >>= 1) s += __shfl_xor_sync(0xffffffffu, s, off);
    if ((t & 31) == 0) red[t >> 5] = s;
    __syncthreads();
    if (t < 8) {
        float r = red[t];
        #pragma unroll
        for (int off = 4; off; off >>= 1) r += __shfl_xor_sync(0xffu, r, off);
        if (t == 0) red[0] = r;
    }
    __syncthreads();
    const float mu = red[0] * (1.0f / Ee);
    __syncthreads();

    float d0 = v0 - mu, d1 = v1 - mu, d2 = v2 - mu;
    float q  = d0*d0 + d1*d1 + d2*d2;
    #pragma unroll
    for (int off = 16; off; off >>= 1) q += __shfl_xor_sync(0xffffffffu, q, off);
    if ((t & 31) == 0) red[t >> 5] = q;
    __syncthreads();
    if (t < 8) {
        float r = red[t];
        #pragma unroll
        for (int off = 4; off; off >>= 1) r += __shfl_xor_sync(0xffu, r, off);
        if (t == 0) red[0] = r;
    }
    __syncthreads();
    const float inv = rsqrtf(red[0] * (1.0f / Ee) + 1e-5f);

    y[t      ] = __float2half_rn(d0 * inv * gamma[t      ] + beta[t      ]);
    y[t + 256] = __float2half_rn(d1 * inv * gamma[t + 256] + beta[t + 256]);
    y[t + 512] = __float2half_rn(d2 * inv * gamma[t + 512] + beta[t + 512]);
}

// ---------------------------------------------------------------------------
// fp16 GEMM: C = A * B^T (+ epilogue). CTA 128x128, K-chunk 64 halves,
// 8 warps (4x2), warp tile 32x64, m16n8k16 + ldmatrix, pitch 72 halves.
// 3-stage cp.async (110.6 KB smem), still 2 CTAs/SM (221 KB < 228 KB).
// ---------------------------------------------------------------------------
enum { EPI_NONE = 0, EPI_BIAS = 1, EPI_BIAS_GELU = 2, EPI_BIAS_RES = 3 };

#define HP      72
#define TILEH   (128*HP)            // halves per matrix per stage
#define STAGEB2 (2*TILEH*2)         // bytes per stage (A+B) = 36864
#define NSTAGE  3
#define SMEMB   (NSTAGE*STAGEB2)    // 110592 B

template <int EPI, int NQKV, bool OUTH>
__global__ __launch_bounds__(256, 2)
void gemm_h(const __half* __restrict__ A,
            const __half* __restrict__ Bq, const __half* __restrict__ Bk,
            const __half* __restrict__ Bv,
            const float* __restrict__ bias, const float* __restrict__ R,
            void* __restrict__ Cq, void* __restrict__ Ck, void* __restrict__ Cv,
            int M, int N, int K)
{
    const __half* Bm = Bq;
    void*         Cout = Cq;
    float qsc = 1.0f;
    if (NQKV == 3) {
        if (blockIdx.z == 1)      { Bm = Bk; Cout = Ck; }
        else if (blockIdx.z == 2) { Bm = Bv; Cout = Cv; }
        else qsc = 0.125f;          // fold attention 1/sqrt(64) into Q
    }

    extern __shared__ char smraw[];
    const uint32_t sBase = smem_u32(smraw);

    const int t    = threadIdx.x;
    const int lane = t & 31;
    const int wid  = t >> 5;
    const int wr   = wid & 3;
    const int wc   = wid >> 2;
    const int mr   = wr * 32;
    const int nc0  = wc * 64;
    const int g    = lane >> 2;
    const int tg   = lane & 3;
    const int q8   = lane >> 3;
    const int lr   = lane & 7;

    const int bm = blockIdx.y * 128;
    const int bn = blockIdx.x * 128;

    float c[2][8][4];
    #pragma unroll
    for (int mt = 0; mt < 2; mt++)
        #pragma unroll
        for (int nt = 0; nt < 8; nt++)
            #pragma unroll
            for (int i = 0; i < 4; i++) c[mt][nt][i] = 0.f;

    auto issue = [&](int ci) {
        const int st = ci % NSTAGE;
        const int k0 = ci << 6;
        const uint32_t dA = sBase + (uint32_t)st * STAGEB2;
        const uint32_t dB = dA + TILEH * 2;
        #pragma unroll
        for (int p = 0; p < 4; p++) {
            const int idx = p * 256 + t;
            const int row = idx >> 3;
            const int cc  = idx & 7;
            const uint32_t so = (uint32_t)(row * HP + cc * 8) * 2;
            cp16(dA + so, A  + (size_t)(bm + row) * K + k0 + cc * 8);
            cp16(dB + so, Bm + (size_t)(bn + row) * K + k0 + cc * 8);
        }
        CP_COMMIT();
    };

    const int nchunk = K >> 6;
    issue(0);
    issue(1);

    #pragma unroll 1
    for (int ci = 0; ci < nchunk; ci++) {
        if (ci + 2 < nchunk)      { issue(ci + 2); CP_WAIT(2); }
        else if (ci + 1 < nchunk) { CP_WAIT(1); }
        else                      { CP_WAIT(0); }
        __syncthreads();

        const uint32_t aU = sBase + (uint32_t)(ci % NSTAGE) * STAGEB2;
        const uint32_t bU = aU + TILEH * 2;

        #pragma unroll
        for (int ks = 0; ks < 4; ks++) {
            uint32_t af[2][4];
            #pragma unroll
            for (int mt = 0; mt < 2; mt++) {
                const int row = mr + mt * 16 + (q8 & 1) * 8 + lr;
                const int col = ks * 16 + (q8 >> 1) * 8;
                ldm_x4(af[mt], aU + (uint32_t)(row * HP + col) * 2);
            }
            #pragma unroll
            for (int ntp = 0; ntp < 4; ntp++) {
                uint32_t bf[4];
                const int rowb = nc0 + ntp * 16 + (q8 >> 1) * 8 + lr;
                const int colb = ks * 16 + (q8 & 1) * 8;
                ldm_x4(bf, bU + (uint32_t)(rowb * HP + colb) * 2);
                mma_f16(c[0][ntp*2],   af[0], bf[0], bf[1]);
                mma_f16(c[1][ntp*2],   af[1], bf[0], bf[1]);
                mma_f16(c[0][ntp*2+1], af[0], bf[2], bf[3]);
                mma_f16(c[1][ntp*2+1], af[1], bf[2], bf[3]);
            }
        }
        __syncthreads();
    }

    #pragma unroll
    for (int mt = 0; mt < 2; mt++) {
        #pragma unroll
        for (int half = 0; half < 2; half++) {
            const int row = bm + mr + mt * 16 + g + half * 8;
            #pragma unroll
            for (int nt = 0; nt < 8; nt++) {
                const int col = bn + nc0 + nt * 8 + 2 * tg;
                float2 v = make_float2(c[mt][nt][half * 2 + 0],
                                       c[mt][nt][half * 2 + 1]);
                if (EPI >= EPI_BIAS) {
                    float2 bb = *(const float2*)(bias + col);
                    v.x += bb.x; v.y += bb.y;
                }
                if (EPI == EPI_BIAS_GELU) {
                    v.x = 0.5f * v.x * (1.0f + erff(v.x * 0.70710678118654752f));
                    v.y = 0.5f * v.y * (1.0f + erff(v.y * 0.70710678118654752f));
                }
                if (EPI == EPI_BIAS_RES) {
                    float2 rr = *(const float2*)(R + (size_t)row * N + col);
                    v.x += rr.x; v.y += rr.y;
                }
                if (NQKV == 3) { v.x *= qsc; v.y *= qsc; }
                if (OUTH) {
                    __half* C = (__half*)Cout;
                    *(__half2*)(C + (size_t)row * N + col) =
                        __floats2half2_rn(v.x, v.y);
                } else {
                    float* C = (float*)Cout;
                    *(float2*)(C + (size_t)row * N + col) = v;
                }
            }
        }
    }
}

// ---------------------------------------------------------------------------
// fp16 flash attention: m16n8k16, P stays in REGISTERS (C-frag of S tile ==
// A-frag of PV tile), V via ldmatrix.trans, fp32 softmax, causal,
// cp.async double-buffered K/V, reversed qt order. smem 46 KB -> 3 CTAs/SM.
// ---------------------------------------------------------------------------
#define FHP 72
#define FHT (64*FHP)                // halves per tile
#define FSMEM (5*FHT*2)             // 46080 B

__global__ __launch_bounds__(128, 3)
void flash_h(const __half* __restrict__ Qg, const __half* __restrict__ Kg,
             const __half* __restrict__ Vg, __half* __restrict__ Og)
{
    extern __shared__ char smraw[];
    const uint32_t sBase = smem_u32(smraw);
    const uint32_t qpU   = sBase + 4 * FHT * 2;

    const int qt = (int)gridDim.x - 1 - (int)blockIdx.x;   // biggest first
    const int h = blockIdx.y, b = blockIdx.z;
    const int q0 = qt * 64;
    const int t = threadIdx.x, wid = t >> 5, lane = t & 31;
    const int g = lane >> 2, tg = lane & 3;
    const int q8 = lane >> 3, lr = lane & 7;
    const int W = wid * 16;
    const int r0l = W + g;
    const size_t base = (size_t)b * Ss * Ee + h * Dd;

    // stage Q
    #pragma unroll
    for (int p = 0; p < 4; p++) {
        const int idx = p * 128 + t, row = idx >> 3, cc = idx & 7;
        cp16(qpU + (uint32_t)(row * FHP + cc * 8) * 2,
             Qg + base + (size_t)(q0 + row) * Ee + cc * 8);
    }
    CP_COMMIT(); CP_WAIT(0);
    __syncthreads();

    uint32_t qf[4][4];
    #pragma unroll
    for (int ks = 0; ks < 4; ks++) {
        const int row = W + (q8 & 1) * 8 + lr;
        const int col = ks * 16 + (q8 >> 1) * 8;
        ldm_x4(qf[ks], qpU + (uint32_t)(row * FHP + col) * 2);
    }

    auto issue = [&](int kt) {
        const int buf = kt & 1;
        const int k0 = kt * 64;
        const uint32_t dK = sBase + (uint32_t)(buf * FHT) * 2;
        const uint32_t dV = sBase + (uint32_t)((2 + buf) * FHT) * 2;
        #pragma unroll
        for (int p = 0; p < 4; p++) {
            const int idx = p * 128 + t, row = idx >> 3, cc = idx & 7;
            const uint32_t so = (uint32_t)(row * FHP + cc * 8) * 2;
            cp16(dK + so, Kg + base + (size_t)(k0 + row) * Ee + cc * 8);
            cp16(dV + so, Vg + base + (size_t)(k0 + row) * Ee + cc * 8);
        }
        CP_COMMIT();
    };

    float m0 = -INFINITY, m1 = -INFINITY, l0 = 0.f, l1 = 0.f;
    float of[8][4];
    #pragma unroll
    for (int nt = 0; nt < 8; nt++) { of[nt][0]=of[nt][1]=of[nt][2]=of[nt][3]=0.f; }

    issue(0);

    for (int kt = 0; kt <= qt; kt++) {
        if (kt < qt) { issue(kt + 1); CP_WAIT(1); }
        else         { CP_WAIT(0); }
        __syncthreads();

        const uint32_t kU = sBase + (uint32_t)((kt & 1) * FHT) * 2;
        const uint32_t vU = sBase + (uint32_t)((2 + (kt & 1)) * FHT) * 2;

        // S = Q @ K^T
        float cS[8][4];
        #pragma unroll
        for (int nt = 0; nt < 8; nt++) { cS[nt][0]=cS[nt][1]=cS[nt][2]=cS[nt][3]=0.f; }
        #pragma unroll
        for (int ks = 0; ks < 4; ks++) {
            #pragma unroll
            for (int ntp = 0; ntp < 4; ntp++) {
                uint32_t bf[4];
                const int rowb = ntp * 16 + (q8 >> 1) * 8 + lr;
                const int colb = ks * 16 + (q8 & 1) * 8;
                ldm_x4(bf, kU + (uint32_t)(rowb * FHP + colb) * 2);
                mma_f16(cS[ntp*2],   qf[ks], bf[0], bf[1]);
                mma_f16(cS[ntp*2+1], qf[ks], bf[2], bf[3]);
            }
        }

        // fp32 online softmax
        const bool diag = (kt == qt);
        float mx0 = -INFINITY, mx1 = -INFINITY;
        #pragma unroll
        for (int nt = 0; nt < 8; nt++) {
            float v0 = cS[nt][0], v1 = cS[nt][1];
            float v2 = cS[nt][2], v3 = cS[nt][3];
            if (diag) {
                const int j0 = nt * 8 + 2 * tg;
                if (j0     > r0l)     v0 = -1e30f;
                if (j0 + 1 > r0l)     v1 = -1e30f;
                if (j0     > r0l + 8) v2 = -1e30f;
                if (j0 + 1 > r0l + 8) v3 = -1e30f;
            }
            cS[nt][0] = v0; cS[nt][1] = v1; cS[nt][2] = v2; cS[nt][3] = v3;
            mx0 = fmaxf(mx0, fmaxf(v0, v1));
            mx1 = fmaxf(mx1, fmaxf(v2, v3));
        }
        mx0 = fmaxf(mx0, __shfl_xor_sync(0xffffffffu, mx0, 1));
        mx0 = fmaxf(mx0, __shfl_xor_sync(0xffffffffu, mx0, 2));
        mx1 = fmaxf(mx1, __shfl_xor_sync(0xffffffffu, mx1, 1));
        mx1 = fmaxf(mx1, __shfl_xor_sync(0xffffffffu, mx1, 2));
        const float mn0 = fmaxf(m0, mx0), mn1 = fmaxf(m1, mx1);
        const float a0 = __expf(m0 - mn0), a1 = __expf(m1 - mn1);
        float rs0 = 0.f, rs1 = 0.f;
        #pragma unroll
        for (int nt = 0; nt < 8; nt++) {
            const float p0e = __expf(cS[nt][0] - mn0);
            const float p1e = __expf(cS[nt][1] - mn0);
            const float p2e = __expf(cS[nt][2] - mn1);
            const float p3e = __expf(cS[nt][3] - mn1);
            cS[nt][0] = p0e; cS[nt][1] = p1e; cS[nt][2] = p2e; cS[nt][3] = p3e;
            rs0 += p0e + p1e; rs1 += p2e + p3e;
        }
        rs0 += __shfl_xor_sync(0xffffffffu, rs0, 1);
        rs0 += __shfl_xor_sync(0xffffffffu, rs0, 2);
        rs1 += __shfl_xor_sync(0xffffffffu, rs1, 1);
        rs1 += __shfl_xor_sync(0xffffffffu, rs1, 2);
        l0 = l0 * a0 + rs0; l1 = l1 * a1 + rs1;
        m0 = mn0; m1 = mn1;
        #pragma unroll
        for (int nt = 0; nt < 8; nt++) {
            of[nt][0] *= a0; of[nt][1] *= a0;
            of[nt][2] *= a1; of[nt][3] *= a1;
        }

        // O += P @ V — P stays in registers: C-frag(S) == A-frag(PV).
        #pragma unroll
        for (int ks = 0; ks < 4; ks++) {
            uint32_t pf[4];
            pf[0] = pack2(cS[2*ks  ][0], cS[2*ks  ][1]);
            pf[1] = pack2(cS[2*ks  ][2], cS[2*ks  ][3]);
            pf[2] = pack2(cS[2*ks+1][0], cS[2*ks+1][1]);
            pf[3] = pack2(cS[2*ks+1][2], cS[2*ks+1][3]);
            #pragma unroll
            for (int ntp = 0; ntp < 4; ntp++) {
                uint32_t vf[4];
                const int rowv = ks * 16 + (q8 & 1) * 8 + lr;
                const int colv = ntp * 16 + (q8 >> 1) * 8;
                ldm_x4t(vf, vU + (uint32_t)(rowv * FHP + colv) * 2);
                mma_f16(of[ntp*2],   pf, vf[0], vf[1]);
                mma_f16(of[ntp*2+1], pf, vf[2], vf[3]);
            }
        }
        __syncthreads();   // protect K/V buffers for next issue()
    }

    const float i0 = 1.f / l0, i1 = 1.f / l1;
    #pragma unroll
    for (int nt = 0; nt < 8; nt++) {
        const int col = nt * 8 + 2 * tg;
        __half* o0 = Og + base + (size_t)(q0 + r0l) * Ee + col;
        __half* o1 = o0 + 8 * Ee;
        *(__half2*)o0 = __floats2half2_rn(of[nt][0] * i0, of[nt][1] * i0);
        *(__half2*)o1 = __floats2half2_rn(of[nt][2] * i1, of[nt][3] * i1);
    }
}

// ---------------------------------------------------------------------------
// Launch
// ---------------------------------------------------------------------------
extern "C" void kernel_launch(void* const* d_in, const int* in_sizes, int n_in,
                              void* d_out, int out_size)
{
    const float* x     = (const float*)d_in[0];
    const float* wq    = (const float*)d_in[1];
    const float* wk    = (const float*)d_in[2];
    const float* wv    = (const float*)d_in[3];
    const float* wo    = (const float*)d_in[4];
    const float* bo    = (const float*)d_in[5];
    const float* w1    = (const float*)d_in[6];
    const float* b1    = (const float*)d_in[7];
    const float* w2    = (const float*)d_in[8];
    const float* b2    = (const float*)d_in[9];
    const float* gamma = (const float*)d_in[10];
    const float* beta  = (const float*)d_in[11];
    float* out = (float*)d_out;

    __half *xnh, *qh, *kh, *vh, *ath, *yh, *hbh;
    __half *wqh, *wkh, *wvh, *woh, *w1h, *w2h;
    float  *res;
    cudaGetSymbolAddress((void**)&xnh, g_xnh);
    cudaGetSymbolAddress((void**)&qh,  g_qh);
    cudaGetSymbolAddress((void**)&kh,  g_kh);
    cudaGetSymbolAddress((void**)&vh,  g_vh);
    cudaGetSymbolAddress((void**)&ath, g_ath);
    cudaGetSymbolAddress((void**)&res, g_res);
    cudaGetSymbolAddress((void**)&yh,  g_yh);
    cudaGetSymbolAddress((void**)&hbh, g_hbh);
    cudaGetSymbolAddress((void**)&wqh, g_wqh);
    cudaGetSymbolAddress((void**)&wkh, g_wkh);
    cudaGetSymbolAddress((void**)&wvh, g_wvh);
    cudaGetSymbolAddress((void**)&woh, g_woh);
    cudaGetSymbolAddress((void**)&w1h, g_w1h);
    cudaGetSymbolAddress((void**)&w2h, g_w2h);

    const dim3 gqkv(Ee / 128, Mrows / 128, 3);
    const dim3 g768(Ee / 128, Mrows / 128);
    const dim3 g3072(FFf / 128, Mrows / 128);

    cudaFuncSetAttribute(flash_h, cudaFuncAttributeMaxDynamicSharedMemorySize, FSMEM);
    cudaFuncSetAttribute(gemm_h<EPI_NONE,3,true>,      cudaFuncAttributeMaxDynamicSharedMemorySize, SMEMB);
    cudaFuncSetAttribute(gemm_h<EPI_BIAS_RES,1,false>, cudaFuncAttributeMaxDynamicSharedMemorySize, SMEMB);
    cudaFuncSetAttribute(gemm_h<EPI_BIAS_GELU,1,true>, cudaFuncAttributeMaxDynamicSharedMemorySize, SMEMB);

    convert_all<<<CONV_BLOCKS, 256>>>(wq, wk, wv, wo, w1, w2,
                                      wqh, wkh, wvh, woh, w1h, w2h);

    ln_kernel<<<Mrows, 256>>>(x, gamma, beta, xnh);

    gemm_h<EPI_NONE,3,true><<<gqkv, 256, SMEMB>>>(xnh, wqh, wkh, wvh, nullptr, nullptr,
                                                  qh, kh, vh, Mrows, Ee, Ee);

    flash_h<<<dim3(Ss / 64, Hh, Bb), 128, FSMEM>>>(qh, kh, vh, ath);

    gemm_h<EPI_BIAS_RES,1,false><<<g768, 256, SMEMB>>>(ath, woh, woh, woh, bo, x,
                                                       res, res, res, Mrows, Ee, Ee);

    ln_kernel<<<Mrows, 256>>>(res, gamma, beta, yh);

    gemm_h<EPI_BIAS_GELU,1,true><<<g3072, 256, SMEMB>>>(yh, w1h, w1h, w1h, b1, nullptr,
                                                        hbh, hbh, hbh, Mrows, FFf, Ee);
    gemm_h<EPI_BIAS_RES,1,false><<<g768, 256, SMEMB>>>(hbh, w2h, w2h, w2h, b2, res,
                                                       out, out, out, Mrows, Ee, FFf);
}

// round 14
// speedup vs baseline: 1.0278x; 1.0278x over previous
#include <cuda_runtime.h>
#include <cuda_fp16.h>
#include <math.h>
#include <stdint.h>

// Problem constants
#define Bb   2
#define Ss   2048
#define Ee   768
#define Hh   12
#define Dd   64
#define FFf  3072
#define Mrows (Bb*Ss)   // 4096

// ---------------------------------------------------------------------------
// Scratch
// ---------------------------------------------------------------------------
__device__ __half g_xnh[Mrows*Ee];
__device__ __half g_qh [Mrows*Ee];
__device__ __half g_kh [Mrows*Ee];
__device__ __half g_vh [Mrows*Ee];
__device__ __half g_ath[Mrows*Ee];
__device__ float  g_res[Mrows*Ee];
__device__ __half g_yh [Mrows*Ee];
__device__ __half g_hbh[Mrows*FFf];
__device__ __half g_wqh[Ee*Ee];
__device__ __half g_wkh[Ee*Ee];
__device__ __half g_wvh[Ee*Ee];
__device__ __half g_woh[Ee*Ee];
__device__ __half g_w1h[FFf*Ee];
__device__ __half g_w2h[Ee*FFf];

// ---------------------------------------------------------------------------
// Helpers
// ---------------------------------------------------------------------------
__device__ __forceinline__ uint32_t smem_u32(const void* p) {
    uint32_t a;
    asm("{ .reg .u64 t; cvta.to.shared.u64 t, %1; cvt.u32.u64 %0, t; }"
        : "=r"(a) : "l"(p));
    return a;
}
__device__ __forceinline__ void cp16(uint32_t dst, const void* src) {
    asm volatile("cp.async.cg.shared.global [%0], [%1], 16;"
                 :: "r"(dst), "l"(src));
}
#define CP_COMMIT() asm volatile("cp.async.commit_group;" ::: "memory")
#define CP_WAIT(n)  asm volatile("cp.async.wait_group %0;" :: "n"(n) : "memory")

__device__ __forceinline__ void mma_f16(float* c, const uint32_t* a,
                                        uint32_t b0, uint32_t b1) {
    asm volatile(
        "mma.sync.aligned.m16n8k16.row.col.f32.f16.f16.f32 "
        "{%0,%1,%2,%3}, {%4,%5,%6,%7}, {%8,%9}, {%0,%1,%2,%3};"
        : "+f"(c[0]), "+f"(c[1]), "+f"(c[2]), "+f"(c[3])
        : "r"(a[0]), "r"(a[1]), "r"(a[2]), "r"(a[3]), "r"(b0), "r"(b1));
}
__device__ __forceinline__ void ldm_x4(uint32_t* r, uint32_t addr) {
    asm volatile("ldmatrix.sync.aligned.m8n8.x4.shared.b16 {%0,%1,%2,%3}, [%4];"
                 : "=r"(r[0]), "=r"(r[1]), "=r"(r[2]), "=r"(r[3]) : "r"(addr));
}
__device__ __forceinline__ void ldm_x4t(uint32_t* r, uint32_t addr) {
    asm volatile("ldmatrix.sync.aligned.m8n8.x4.trans.shared.b16 {%0,%1,%2,%3}, [%4];"
                 : "=r"(r[0]), "=r"(r[1]), "=r"(r[2]), "=r"(r[3]) : "r"(addr));
}
__device__ __forceinline__ uint32_t pack2(float a, float b) {
    __half2 h = __floats2half2_rn(a, b);
    return *(uint32_t*)&h;
}

// ---------------------------------------------------------------------------
// Fused weight conversion f32 -> f16 (one launch)
// ---------------------------------------------------------------------------
__global__ void convert_all(const float* __restrict__ wq, const float* __restrict__ wk,
                            const float* __restrict__ wv, const float* __restrict__ wo,
                            const float* __restrict__ w1, const float* __restrict__ w2,
                            __half* __restrict__ dq, __half* __restrict__ dk,
                            __half* __restrict__ dv, __half* __restrict__ dwo,
                            __half* __restrict__ d1, __half* __restrict__ d2)
{
    const int E4 = Ee * Ee / 4;
    const int F4 = (FFf * Ee) / 4;
    int i = blockIdx.x * blockDim.x + threadIdx.x;
    const float* s; __half* d;
    if      (i < E4)          { s = wq; d = dq; }
    else if (i < 2*E4)        { s = wk; d = dk;  i -= E4; }
    else if (i < 3*E4)        { s = wv; d = dv;  i -= 2*E4; }
    else if (i < 4*E4)        { s = wo; d = dwo; i -= 3*E4; }
    else if (i < 4*E4 + F4)   { s = w1; d = d1;  i -= 4*E4; }
    else                      { s = w2; d = d2;  i -= 4*E4 + F4; }
    float4 v = ((const float4*)s)[i];
    __half2* o = (__half2*)(d + i * 4);
    o[0] = __floats2half2_rn(v.x, v.y);
    o[1] = __floats2half2_rn(v.z, v.w);
}
#define CONV_BLOCKS ((4*(Ee*Ee/4) + 2*((FFf*Ee)/4)) / 256)

// ---------------------------------------------------------------------------
// LayerNorm (f32 in, f16 out)
// ---------------------------------------------------------------------------
__global__ void ln_kernel(const float* __restrict__ X,
                          const float* __restrict__ gamma,
                          const float* __restrict__ beta,
                          __half* __restrict__ Y)
{
    const int row = blockIdx.x;
    const float* x = X + (size_t)row * Ee;
    __half*      y = Y + (size_t)row * Ee;
    const int t = threadIdx.x;

    float v0 = x[t], v1 = x[t + 256], v2 = x[t + 512];
    float s  = v0 + v1 + v2;

    __shared__ float red[8];
    #pragma unroll
    for (int off = 16; off; off >>= 1) s += __shfl_xor_sync(0xffffffffu, s, off);
    if ((t & 31) == 0) red[t >> 5] = s;
    __syncthreads();
    if (t < 8) {
        float r = red[t];
        #pragma unroll
        for (int off = 4; off; off >>= 1) r += __shfl_xor_sync(0xffu, r, off);
        if (t == 0) red[0] = r;
    }
    __syncthreads();
    const float mu = red[0] * (1.0f / Ee);
    __syncthreads();

    float d0 = v0 - mu, d1 = v1 - mu, d2 = v2 - mu;
    float q  = d0*d0 + d1*d1 + d2*d2;
    #pragma unroll
    for (int off = 16; off; off >>= 1) q += __shfl_xor_sync(0xffffffffu, q, off);
    if ((t & 31) == 0) red[t >> 5] = q;
    __syncthreads();
    if (t < 8) {
        float r = red[t];
        #pragma unroll
        for (int off = 4; off; off >>= 1) r += __shfl_xor_sync(0xffu, r, off);
        if (t == 0) red[0] = r;
    }
    __syncthreads();
    const float inv = rsqrtf(red[0] * (1.0f / Ee) + 1e-5f);

    y[t      ] = __float2half_rn(d0 * inv * gamma[t      ] + beta[t      ]);
    y[t + 256] = __float2half_rn(d1 * inv * gamma[t + 256] + beta[t + 256]);
    y[t + 512] = __float2half_rn(d2 * inv * gamma[t + 512] + beta[t + 512]);
}

// ---------------------------------------------------------------------------
// fp16 GEMM: C = A * B^T (+ epilogue). CTA 128x128, K-chunk 64 halves,
// 8 warps (4x2), warp tile 32x64, m16n8k16 + ldmatrix, pitch 72 halves.
// 3-stage cp.async, ONE __syncthreads per chunk:
//   CP_WAIT -> sync -> issue(ci+2) -> compute.
// issue(ci+2) overwrites stage (ci-1)%3, whose readers all passed this sync.
// ---------------------------------------------------------------------------
enum { EPI_NONE = 0, EPI_BIAS = 1, EPI_BIAS_GELU = 2, EPI_BIAS_RES = 3 };

#define HP      72
#define TILEH   (128*HP)            // halves per matrix per stage
#define STAGEB2 (2*TILEH*2)         // bytes per stage (A+B) = 36864
#define NSTAGE  3
#define SMEMB   (NSTAGE*STAGEB2)    // 110592 B -> 2 CTAs/SM

template <int EPI, int NQKV, bool OUTH>
__global__ __launch_bounds__(256, 2)
void gemm_h(const __half* __restrict__ A,
            const __half* __restrict__ Bq, const __half* __restrict__ Bk,
            const __half* __restrict__ Bv,
            const float* __restrict__ bias, const float* __restrict__ R,
            void* __restrict__ Cq, void* __restrict__ Ck, void* __restrict__ Cv,
            int M, int N, int K)
{
    const __half* Bm = Bq;
    void*         Cout = Cq;
    float qsc = 1.0f;
    if (NQKV == 3) {
        if (blockIdx.z == 1)      { Bm = Bk; Cout = Ck; }
        else if (blockIdx.z == 2) { Bm = Bv; Cout = Cv; }
        else qsc = 0.125f;          // fold attention 1/sqrt(64) into Q
    }

    extern __shared__ char smraw[];
    const uint32_t sBase = smem_u32(smraw);

    const int t    = threadIdx.x;
    const int lane = t & 31;
    const int wid  = t >> 5;
    const int wr   = wid & 3;
    const int wc   = wid >> 2;
    const int mr   = wr * 32;
    const int nc0  = wc * 64;
    const int g    = lane >> 2;
    const int tg   = lane & 3;
    const int q8   = lane >> 3;
    const int lr   = lane & 7;

    const int bm = blockIdx.y * 128;
    const int bn = blockIdx.x * 128;

    float c[2][8][4];
    #pragma unroll
    for (int mt = 0; mt < 2; mt++)
        #pragma unroll
        for (int nt = 0; nt < 8; nt++)
            #pragma unroll
            for (int i = 0; i < 4; i++) c[mt][nt][i] = 0.f;

    auto issue = [&](int ci) {
        const int st = ci % NSTAGE;
        const int k0 = ci << 6;
        const uint32_t dA = sBase + (uint32_t)st * STAGEB2;
        const uint32_t dB = dA + TILEH * 2;
        #pragma unroll
        for (int p = 0; p < 4; p++) {
            const int idx = p * 256 + t;
            const int row = idx >> 3;
            const int cc  = idx & 7;
            const uint32_t so = (uint32_t)(row * HP + cc * 8) * 2;
            cp16(dA + so, A  + (size_t)(bm + row) * K + k0 + cc * 8);
            cp16(dB + so, Bm + (size_t)(bn + row) * K + k0 + cc * 8);
        }
        CP_COMMIT();
    };

    const int nchunk = K >> 6;
    issue(0);
    issue(1);

    #pragma unroll 1
    for (int ci = 0; ci < nchunk; ci++) {
        if (ci + 1 < nchunk) { CP_WAIT(1); }
        else                 { CP_WAIT(0); }
        __syncthreads();
        if (ci + 2 < nchunk) issue(ci + 2);

        const uint32_t aU = sBase + (uint32_t)(ci % NSTAGE) * STAGEB2;
        const uint32_t bU = aU + TILEH * 2;

        #pragma unroll
        for (int ks = 0; ks < 4; ks++) {
            uint32_t af[2][4];
            #pragma unroll
            for (int mt = 0; mt < 2; mt++) {
                const int row = mr + mt * 16 + (q8 & 1) * 8 + lr;
                const int col = ks * 16 + (q8 >> 1) * 8;
                ldm_x4(af[mt], aU + (uint32_t)(row * HP + col) * 2);
            }
            #pragma unroll
            for (int ntp = 0; ntp < 4; ntp++) {
                uint32_t bf[4];
                const int rowb = nc0 + ntp * 16 + (q8 >> 1) * 8 + lr;
                const int colb = ks * 16 + (q8 & 1) * 8;
                ldm_x4(bf, bU + (uint32_t)(rowb * HP + colb) * 2);
                mma_f16(c[0][ntp*2],   af[0], bf[0], bf[1]);
                mma_f16(c[1][ntp*2],   af[1], bf[0], bf[1]);
                mma_f16(c[0][ntp*2+1], af[0], bf[2], bf[3]);
                mma_f16(c[1][ntp*2+1], af[1], bf[2], bf[3]);
            }
        }
        // no trailing sync: next iteration's barrier protects stage reuse
    }

    #pragma unroll
    for (int mt = 0; mt < 2; mt++) {
        #pragma unroll
        for (int half = 0; half < 2; half++) {
            const int row = bm + mr + mt * 16 + g + half * 8;
            #pragma unroll
            for (int nt = 0; nt < 8; nt++) {
                const int col = bn + nc0 + nt * 8 + 2 * tg;
                float2 v = make_float2(c[mt][nt][half * 2 + 0],
                                       c[mt][nt][half * 2 + 1]);
                if (EPI >= EPI_BIAS) {
                    float2 bb = *(const float2*)(bias + col);
                    v.x += bb.x; v.y += bb.y;
                }
                if (EPI == EPI_BIAS_GELU) {
                    v.x = 0.5f * v.x * (1.0f + erff(v.x * 0.70710678118654752f));
                    v.y = 0.5f * v.y * (1.0f + erff(v.y * 0.70710678118654752f));
                }
                if (EPI == EPI_BIAS_RES) {
                    float2 rr = *(const float2*)(R + (size_t)row * N + col);
                    v.x += rr.x; v.y += rr.y;
                }
                if (NQKV == 3) { v.x *= qsc; v.y *= qsc; }
                if (OUTH) {
                    __half* C = (__half*)Cout;
                    *(__half2*)(C + (size_t)row * N + col) =
                        __floats2half2_rn(v.x, v.y);
                } else {
                    float* C = (float*)Cout;
                    *(float2*)(C + (size_t)row * N + col) = v;
                }
            }
        }
    }
}

// ---------------------------------------------------------------------------
// fp16 flash attention: m16n8k16, register-resident P, V via ldmatrix.trans,
// 3-buffer K/V ring + ONE __syncthreads per KV tile, fp32 softmax, causal,
// reversed qt order. smem: 3*(K+V) + Q = 64512 B -> 3 CTAs/SM.
// ---------------------------------------------------------------------------
#define FHP 72
#define FHT (64*FHP)                // halves per tile
#define FSMEM ((6*FHT + FHT) * 2)   // 64512 B

__global__ __launch_bounds__(128, 3)
void flash_h(const __half* __restrict__ Qg, const __half* __restrict__ Kg,
             const __half* __restrict__ Vg, __half* __restrict__ Og)
{
    extern __shared__ char smraw[];
    const uint32_t sBase = smem_u32(smraw);
    const uint32_t qpU   = sBase + 6 * FHT * 2;

    const int qt = (int)gridDim.x - 1 - (int)blockIdx.x;   // biggest first
    const int h = blockIdx.y, b = blockIdx.z;
    const int q0 = qt * 64;
    const int t = threadIdx.x, wid = t >> 5, lane = t & 31;
    const int g = lane >> 2, tg = lane & 3;
    const int q8 = lane >> 3, lr = lane & 7;
    const int W = wid * 16;
    const int r0l = W + g;
    const size_t base = (size_t)b * Ss * Ee + h * Dd;

    // stage Q
    #pragma unroll
    for (int p = 0; p < 4; p++) {
        const int idx = p * 128 + t, row = idx >> 3, cc = idx & 7;
        cp16(qpU + (uint32_t)(row * FHP + cc * 8) * 2,
             Qg + base + (size_t)(q0 + row) * Ee + cc * 8);
    }
    CP_COMMIT();

    auto issue = [&](int kt) {
        const int buf = kt % 3;
        const int k0 = kt * 64;
        const uint32_t dK = sBase + (uint32_t)(buf * 2 * FHT) * 2;
        const uint32_t dV = dK + FHT * 2;
        #pragma unroll
        for (int p = 0; p < 4; p++) {
            const int idx = p * 128 + t, row = idx >> 3, cc = idx & 7;
            const uint32_t so = (uint32_t)(row * FHP + cc * 8) * 2;
            cp16(dK + so, Kg + base + (size_t)(k0 + row) * Ee + cc * 8);
            cp16(dV + so, Vg + base + (size_t)(k0 + row) * Ee + cc * 8);
        }
        CP_COMMIT();
    };

    issue(0);
    if (qt >= 1) issue(1);

    // Q fragments: wait for Q group (issued before K/V groups)
    // groups pending: Q, K0, (K1) -> wait until <= (#KV groups) remain
    if (qt >= 1) { CP_WAIT(2); } else { CP_WAIT(1); }
    __syncthreads();
    uint32_t qf[4][4];
    #pragma unroll
    for (int ks = 0; ks < 4; ks++) {
        const int row = W + (q8 & 1) * 8 + lr;
        const int col = ks * 16 + (q8 >> 1) * 8;
        ldm_x4(qf[ks], qpU + (uint32_t)(row * FHP + col) * 2);
    }

    float m0 = -INFINITY, m1 = -INFINITY, l0 = 0.f, l1 = 0.f;
    float of[8][4];
    #pragma unroll
    for (int nt = 0; nt < 8; nt++) { of[nt][0]=of[nt][1]=of[nt][2]=of[nt][3]=0.f; }

    for (int kt = 0; kt <= qt; kt++) {
        if (kt < qt) { CP_WAIT(1); }
        else         { CP_WAIT(0); }
        __syncthreads();
        if (kt + 2 <= qt) issue(kt + 2);

        const uint32_t kU = sBase + (uint32_t)((kt % 3) * 2 * FHT) * 2;
        const uint32_t vU = kU + FHT * 2;

        // S = Q @ K^T
        float cS[8][4];
        #pragma unroll
        for (int nt = 0; nt < 8; nt++) { cS[nt][0]=cS[nt][1]=cS[nt][2]=cS[nt][3]=0.f; }
        #pragma unroll
        for (int ks = 0; ks < 4; ks++) {
            #pragma unroll
            for (int ntp = 0; ntp < 4; ntp++) {
                uint32_t bf[4];
                const int rowb = ntp * 16 + (q8 >> 1) * 8 + lr;
                const int colb = ks * 16 + (q8 & 1) * 8;
                ldm_x4(bf, kU + (uint32_t)(rowb * FHP + colb) * 2);
                mma_f16(cS[ntp*2],   qf[ks], bf[0], bf[1]);
                mma_f16(cS[ntp*2+1], qf[ks], bf[2], bf[3]);
            }
        }

        // fp32 online softmax
        const bool diag = (kt == qt);
        float mx0 = -INFINITY, mx1 = -INFINITY;
        #pragma unroll
        for (int nt = 0; nt < 8; nt++) {
            float v0 = cS[nt][0], v1 = cS[nt][1];
            float v2 = cS[nt][2], v3 = cS[nt][3];
            if (diag) {
                const int j0 = nt * 8 + 2 * tg;
                if (j0     > r0l)     v0 = -1e30f;
                if (j0 + 1 > r0l)     v1 = -1e30f;
                if (j0     > r0l + 8) v2 = -1e30f;
                if (j0 + 1 > r0l + 8) v3 = -1e30f;
            }
            cS[nt][0] = v0; cS[nt][1] = v1; cS[nt][2] = v2; cS[nt][3] = v3;
            mx0 = fmaxf(mx0, fmaxf(v0, v1));
            mx1 = fmaxf(mx1, fmaxf(v2, v3));
        }
        mx0 = fmaxf(mx0, __shfl_xor_sync(0xffffffffu, mx0, 1));
        mx0 = fmaxf(mx0, __shfl_xor_sync(0xffffffffu, mx0, 2));
        mx1 = fmaxf(mx1, __shfl_xor_sync(0xffffffffu, mx1, 1));
        mx1 = fmaxf(mx1, __shfl_xor_sync(0xffffffffu, mx1, 2));
        const float mn0 = fmaxf(m0, mx0), mn1 = fmaxf(m1, mx1);
        const float a0 = __expf(m0 - mn0), a1 = __expf(m1 - mn1);
        float rs0 = 0.f, rs1 = 0.f;
        #pragma unroll
        for (int nt = 0; nt < 8; nt++) {
            const float p0e = __expf(cS[nt][0] - mn0);
            const float p1e = __expf(cS[nt][1] - mn0);
            const float p2e = __expf(cS[nt][2] - mn1);
            const float p3e = __expf(cS[nt][3] - mn1);
            cS[nt][0] = p0e; cS[nt][1] = p1e; cS[nt][2] = p2e; cS[nt][3] = p3e;
            rs0 += p0e + p1e; rs1 += p2e + p3e;
        }
        rs0 += __shfl_xor_sync(0xffffffffu, rs0, 1);
        rs0 += __shfl_xor_sync(0xffffffffu, rs0, 2);
        rs1 += __shfl_xor_sync(0xffffffffu, rs1, 1);
        rs1 += __shfl_xor_sync(0xffffffffu, rs1, 2);
        l0 = l0 * a0 + rs0; l1 = l1 * a1 + rs1;
        m0 = mn0; m1 = mn1;
        #pragma unroll
        for (int nt = 0; nt < 8; nt++) {
            of[nt][0] *= a0; of[nt][1] *= a0;
            of[nt][2] *= a1; of[nt][3] *= a1;
        }

        // O += P @ V — P stays in registers (C-frag == A-frag layout)
        #pragma unroll
        for (int ks = 0; ks < 4; ks++) {
            uint32_t pf[4];
            pf[0] = pack2(cS[2*ks  ][0], cS[2*ks  ][1]);
            pf[1] = pack2(cS[2*ks  ][2], cS[2*ks  ][3]);
            pf[2] = pack2(cS[2*ks+1][0], cS[2*ks+1][1]);
            pf[3] = pack2(cS[2*ks+1][2], cS[2*ks+1][3]);
            #pragma unroll
            for (int ntp = 0; ntp < 4; ntp++) {
                uint32_t vf[4];
                const int rowv = ks * 16 + (q8 & 1) * 8 + lr;
                const int colv = ntp * 16 + (q8 >> 1) * 8;
                ldm_x4t(vf, vU + (uint32_t)(rowv * FHP + colv) * 2);
                mma_f16(of[ntp*2],   pf, vf[0], vf[1]);
                mma_f16(of[ntp*2+1], pf, vf[2], vf[3]);
            }
        }
        // no trailing sync: 3-buffer ring + next iteration's barrier
    }

    const float i0 = 1.f / l0, i1 = 1.f / l1;
    #pragma unroll
    for (int nt = 0; nt < 8; nt++) {
        const int col = nt * 8 + 2 * tg;
        __half* o0 = Og + base + (size_t)(q0 + r0l) * Ee + col;
        __half* o1 = o0 + 8 * Ee;
        *(__half2*)o0 = __floats2half2_rn(of[nt][0] * i0, of[nt][1] * i0);
        *(__half2*)o1 = __floats2half2_rn(of[nt][2] * i1, of[nt][3] * i1);
    }
}

// ---------------------------------------------------------------------------
// Launch
// ---------------------------------------------------------------------------
extern "C" void kernel_launch(void* const* d_in, const int* in_sizes, int n_in,
                              void* d_out, int out_size)
{
    const float* x     = (const float*)d_in[0];
    const float* wq    = (const float*)d_in[1];
    const float* wk    = (const float*)d_in[2];
    const float* wv    = (const float*)d_in[3];
    const float* wo    = (const float*)d_in[4];
    const float* bo    = (const float*)d_in[5];
    const float* w1    = (const float*)d_in[6];
    const float* b1    = (const float*)d_in[7];
    const float* w2    = (const float*)d_in[8];
    const float* b2    = (const float*)d_in[9];
    const float* gamma = (const float*)d_in[10];
    const float* beta  = (const float*)d_in[11];
    float* out = (float*)d_out;

    __half *xnh, *qh, *kh, *vh, *ath, *yh, *hbh;
    __half *wqh, *wkh, *wvh, *woh, *w1h, *w2h;
    float  *res;
    cudaGetSymbolAddress((void**)&xnh, g_xnh);
    cudaGetSymbolAddress((void**)&qh,  g_qh);
    cudaGetSymbolAddress((void**)&kh,  g_kh);
    cudaGetSymbolAddress((void**)&vh,  g_vh);
    cudaGetSymbolAddress((void**)&ath, g_ath);
    cudaGetSymbolAddress((void**)&res, g_res);
    cudaGetSymbolAddress((void**)&yh,  g_yh);
    cudaGetSymbolAddress((void**)&hbh, g_hbh);
    cudaGetSymbolAddress((void**)&wqh, g_wqh);
    cudaGetSymbolAddress((void**)&wkh, g_wkh);
    cudaGetSymbolAddress((void**)&wvh, g_wvh);
    cudaGetSymbolAddress((void**)&woh, g_woh);
    cudaGetSymbolAddress((void**)&w1h, g_w1h);
    cudaGetSymbolAddress((void**)&w2h, g_w2h);

    const dim3 gqkv(Ee / 128, Mrows / 128, 3);
    const dim3 g768(Ee / 128, Mrows / 128);
    const dim3 g3072(FFf / 128, Mrows / 128);

    cudaFuncSetAttribute(flash_h, cudaFuncAttributeMaxDynamicSharedMemorySize, FSMEM);
    cudaFuncSetAttribute(gemm_h<EPI_NONE,3,true>,      cudaFuncAttributeMaxDynamicSharedMemorySize, SMEMB);
    cudaFuncSetAttribute(gemm_h<EPI_BIAS_RES,1,false>, cudaFuncAttributeMaxDynamicSharedMemorySize, SMEMB);
    cudaFuncSetAttribute(gemm_h<EPI_BIAS_GELU,1,true>, cudaFuncAttributeMaxDynamicSharedMemorySize, SMEMB);

    convert_all<<<CONV_BLOCKS, 256>>>(wq, wk, wv, wo, w1, w2,
                                      wqh, wkh, wvh, woh, w1h, w2h);

    ln_kernel<<<Mrows, 256>>>(x, gamma, beta, xnh);

    gemm_h<EPI_NONE,3,true><<<gqkv, 256, SMEMB>>>(xnh, wqh, wkh, wvh, nullptr, nullptr,
                                                  qh, kh, vh, Mrows, Ee, Ee);

    flash_h<<<dim3(Ss / 64, Hh, Bb), 128, FSMEM>>>(qh, kh, vh, ath);

    gemm_h<EPI_BIAS_RES,1,false><<<g768, 256, SMEMB>>>(ath, woh, woh, woh, bo, x,
                                                       res, res, res, Mrows, Ee, Ee);

    ln_kernel<<<Mrows, 256>>>(res, gamma, beta, yh);

    gemm_h<EPI_BIAS_GELU,1,true><<<g3072, 256, SMEMB>>>(yh, w1h, w1h, w1h, b1, nullptr,
                                                        hbh, hbh, hbh, Mrows, FFf, Ee);
    gemm_h<EPI_BIAS_RES,1,false><<<g768, 256, SMEMB>>>(hbh, w2h, w2h, w2h, b2, res,
                                                       out, out, out, Mrows, Ee, FFf);
}